// round 14
// baseline (speedup 1.0000x reference)
#include <cuda_runtime.h>

#define EPS_VAL 1e-5f
#define NT      128            // 4 warps/block
#define WPB     4
#define NG      4
#define VPT     10             // max float4 vectors per lane (dim <= 1280)

#define BFLY(val)                                    \
    _Pragma("unroll")                                \
    for (int _o = 16; _o > 0; _o >>= 1)              \
        val += __shfl_xor_sync(0xffffffffu, val, _o);

__device__ __forceinline__ float sel4(int g, float a, float b, float c, float d) {
    float lo = (g == 0) ? a : b;
    float hi = (g == 2) ? c : d;
    return (g < 2) ? lo : hi;
}

__device__ __forceinline__ void cp16(float4* dst_smem, const float4* src) {
    unsigned d = (unsigned)__cvta_generic_to_shared(dst_smem);
    asm volatile("cp.async.cg.shared.global [%0], [%1], 16;\n" :: "r"(d), "l"(src));
}
__device__ __forceinline__ void cp_commit() { asm volatile("cp.async.commit_group;\n"); }
__device__ __forceinline__ void cp_wait1()  { asm volatile("cp.async.wait_group 1;\n"); }

extern __shared__ float4 smem_dyn[];
// layout: [WPB*2*nvec] row buffers | [nvec] w | [nvec] b | [nvec ints] gv

__global__ void __launch_bounds__(NT, 4)
eqln_kernel(const float* __restrict__ x,
            const float* __restrict__ weight,
            const float* __restrict__ bias,
            const int*   __restrict__ group_idx,
            const int*   __restrict__ irrep_idx,
            const int*   __restrict__ scalar_indices,
            float*       __restrict__ out,
            int np, int dim, int nscalar)
{
    __shared__ float s_cnt[NG], s_scnt[NG];
    __shared__ float s_icnt[NG], s_iscnt[NG], s_scf[NG];
    __shared__ int   s_umask;

    const int tid  = threadIdx.x;
    const int nvec = dim >> 2;

    float4* s_w  = smem_dyn + (size_t)(WPB * 2) * nvec;
    float4* s_b  = s_w + nvec;
    int*    s_gv = (int*)(s_b + nvec);

    // ---------------- per-block metadata setup (amortized over many rows) -------
    if (tid < NG) { s_cnt[tid] = 0.f; s_scnt[tid] = 0.f; }
    __syncthreads();
    for (int i = tid; i < dim; i += NT) {
        int g = group_idx[i];
        atomicAdd(&s_cnt[g], 1.f);
        ((float*)s_w)[i] = weight[irrep_idx[i]];
        ((float*)s_b)[i] = 0.f;
        if ((i & 3) == 0) s_gv[i >> 2] = g;
    }
    __syncthreads();
    for (int k = tid; k < nscalar; k += NT) {
        int idx = scalar_indices[k];
        ((float*)s_b)[idx] = bias[k];
        atomicAdd(&s_scnt[group_idx[idx]], 1.f);
    }
    __syncthreads();
    if (tid < NG) {
        s_icnt[tid]  = 1.f / s_cnt[tid];
        s_iscnt[tid] = (s_scnt[tid] > 0.f) ? (1.f / s_scnt[tid]) : 0.f;
        s_scf[tid]   = s_scnt[tid];
    }
    if (tid == 0) {
        int m = 0;
        for (int g = 0; g < NG; g++) if (s_scnt[g] > 0.f) m |= (1 << g);
        s_umask = m;
    }
    __syncthreads();

    // ---------------- row-invariant per-lane state ------------------------------
    const int lane = tid & 31;
    const int wid  = tid >> 5;

    unsigned gp = 0;                 // packed group id per vector: 2 bits x VPT
    #pragma unroll
    for (int i = 0; i < VPT; i++) {
        int vi = lane + 32 * i;
        int g  = (vi < nvec) ? s_gv[vi] : 3;
        gp |= (unsigned)g << (2 * i);
    }
    const int umask = s_umask;
    const int totw  = gridDim.x * WPB;

    float4* buf0 = smem_dyn + (size_t)(wid * 2) * nvec;   // per-warp double buffer
    float4* buf1 = buf0 + nvec;

    // ---------------- warp-per-row loop: cp.async double-buffered, no barriers --
    int row = blockIdx.x * WPB + wid;

    // prime: prefetch first row into buf0
    {
        if (row < np) {
            const float4* xr = (const float4*)(x + (size_t)row * dim);
            #pragma unroll
            for (int i = 0; i < VPT; i++) {
                int vi = lane + 32 * i;
                if (vi < nvec) cp16(&buf0[vi], &xr[vi]);
            }
        }
        cp_commit();
    }

    int pb = 0;
    for (; row < np; row += totw) {
        // prefetch next row into the other buffer
        {
            int nrow = row + totw;
            float4* nb = pb ? buf0 : buf1;
            if (nrow < np) {
                const float4* xr = (const float4*)(x + (size_t)nrow * dim);
                #pragma unroll
                for (int i = 0; i < VPT; i++) {
                    int vi = lane + 32 * i;
                    if (vi < nvec) cp16(&nb[vi], &xr[vi]);
                }
            }
            cp_commit();
        }
        cp_wait1();          // current row's group (older of the two) is complete
        __syncwarp();

        const float4* sb = pb ? buf1 : buf0;

        // pass 1: accumulate per-group sum(x^2); sum(x) for scalar groups
        float a0 = 0.f, a1 = 0.f, a2 = 0.f, a3 = 0.f;
        float u0 = 0.f, u1 = 0.f, u2 = 0.f, u3 = 0.f;
        #pragma unroll
        for (int i = 0; i < VPT; i++) {
            int vi = lane + 32 * i;
            if (vi < nvec) {
                float4 t = sb[vi];
                float s2 = t.x * t.x + t.y * t.y + t.z * t.z + t.w * t.w;
                float s1 = t.x + t.y + t.z + t.w;
                int g = (gp >> (2 * i)) & 3;
                if      (g == 0) { a0 += s2; if (umask & 1) u0 += s1; }
                else if (g == 1) { a1 += s2; if (umask & 2) u1 += s1; }
                else if (g == 2) { a2 += s2; if (umask & 4) u2 += s1; }
                else             { a3 += s2; if (umask & 8) u3 += s1; }
            }
        }

        BFLY(a0); BFLY(a1); BFLY(a2); BFLY(a3);
        if (umask & 1) { BFLY(u0); }
        if (umask & 2) { BFLY(u1); }
        if (umask & 4) { BFLY(u2); }
        if (umask & 8) { BFLY(u3); }

        // per-group stats: m_g = scalar mean (0 for non-scalar groups)
        // var_g = (ssq_g + m*(m*scnt_g - 2*ssum_g)) / cnt_g
        float m0 = u0 * s_iscnt[0], m1 = u1 * s_iscnt[1];
        float m2 = u2 * s_iscnt[2], m3 = u3 * s_iscnt[3];
        float r0 = rsqrtf(fmaf(m0, fmaf(m0, s_scf[0], -2.f * u0), a0) * s_icnt[0] + EPS_VAL);
        float r1 = rsqrtf(fmaf(m1, fmaf(m1, s_scf[1], -2.f * u1), a1) * s_icnt[1] + EPS_VAL);
        float r2 = rsqrtf(fmaf(m2, fmaf(m2, s_scf[2], -2.f * u2), a2) * s_icnt[2] + EPS_VAL);
        float r3 = rsqrtf(fmaf(m3, fmaf(m3, s_scf[3], -2.f * u3), a3) * s_icnt[3] + EPS_VAL);

        // pass 2: re-read row from SMEM, normalize, store
        float4* orow = (float4*)(out + (size_t)row * dim);
        #pragma unroll
        for (int i = 0; i < VPT; i++) {
            int vi = lane + 32 * i;
            if (vi < nvec) {
                int g = (gp >> (2 * i)) & 3;
                float mm = sel4(g, m0, m1, m2, m3);
                float rr = sel4(g, r0, r1, r2, r3);
                float4 t = sb[vi];
                float4 w = s_w[vi];
                float4 b = s_b[vi];
                float4 o;
                o.x = (t.x - mm) * rr * w.x + b.x;
                o.y = (t.y - mm) * rr * w.y + b.y;
                o.z = (t.z - mm) * rr * w.z + b.z;
                o.w = (t.w - mm) * rr * w.w + b.w;
                orow[vi] = o;
            }
        }
        pb ^= 1;
    }
}

extern "C" void kernel_launch(void* const* d_in, const int* in_sizes, int n_in,
                              void* d_out, int out_size)
{
    const float* x              = (const float*)d_in[0];
    const float* weight         = (const float*)d_in[1];
    const float* bias           = (const float*)d_in[2];
    const int*   group_idx      = (const int*)  d_in[3];
    const int*   irrep_idx      = (const int*)  d_in[4];
    const int*   scalar_indices = (const int*)  d_in[5];
    // d_in[6] = scalar_group, unused (each scalar group coincides with one irrep group)

    const int dim     = in_sizes[3];            // len(group_idx) == feature dim
    const int np      = in_sizes[0] / dim;      // number of points
    const int nscalar = in_sizes[5];
    const int nvec    = dim >> 2;

    // dynamic smem: WPB*2 row buffers + w + b (float4) + gv (int)
    size_t smbytes = (size_t)(WPB * 2 + 2) * nvec * sizeof(float4)
                   + (size_t)nvec * sizeof(int) + 16;
    if (smbytes > 48 * 1024)
        cudaFuncSetAttribute(eqln_kernel,
                             cudaFuncAttributeMaxDynamicSharedMemorySize,
                             (int)smbytes);

    int grid = 152 * 4;                         // 4 resident blocks/SM (smem-limited)
    int maxb = (np + WPB - 1) / WPB;
    if (grid > maxb) grid = maxb;

    eqln_kernel<<<grid, NT, smbytes>>>(x, weight, bias,
                                       group_idx, irrep_idx, scalar_indices,
                                       (float*)d_out, np, dim, nscalar);
}

// round 15
// speedup vs baseline: 1.3968x; 1.3968x over previous
#include <cuda_runtime.h>

#define EPS_VAL 1e-5f
#define NT      256            // 8 warps/block
#define WPB     8
#define MAXVEC  320
#define NG      4
#define VPT     10             // max float4 vectors per lane (dim <= 1280)

#define BFLY(val)                                    \
    _Pragma("unroll")                                \
    for (int _o = 16; _o > 0; _o >>= 1)              \
        val += __shfl_xor_sync(0xffffffffu, val, _o);

__device__ __forceinline__ float sel4(int g, float a, float b, float c, float d) {
    float lo = (g == 0) ? a : b;
    float hi = (g == 2) ? c : d;
    return (g < 2) ? lo : hi;
}

__global__ void __launch_bounds__(NT, 3)       // R6 residency: 3 blocks = 24 warps/SM
eqln_kernel(const float* __restrict__ x,
            const float* __restrict__ weight,
            const float* __restrict__ bias,
            const int*   __restrict__ group_idx,
            const int*   __restrict__ irrep_idx,
            const int*   __restrict__ scalar_indices,
            float*       __restrict__ out,
            int np, int dim, int nscalar)
{
    __shared__ float4 s_w[MAXVEC];       // weight[irrep_idx[i]] per element
    __shared__ float4 s_b[MAXVEC];       // bias scattered to full dim (0 elsewhere)
    __shared__ int    s_gv[MAXVEC];      // group id per float4 (groups 16B-aligned)
    __shared__ float  s_cnt[NG], s_scnt[NG];
    __shared__ float  s_icnt[NG], s_iscnt[NG], s_scf[NG];
    __shared__ int    s_umask, s_nonuni;

    const int tid  = threadIdx.x;
    const int nvec = dim >> 2;

    // ---------------- per-block metadata setup (amortized over ~180 rows) -------
    if (tid < NG) { s_cnt[tid] = 0.f; s_scnt[tid] = 0.f; }
    if (tid == 0) s_nonuni = 0;
    __syncthreads();

    const float w0 = weight[0];
    int bad = 0;
    for (int i = tid; i < dim; i += NT) {
        int g = group_idx[i];
        atomicAdd(&s_cnt[g], 1.f);
        float wv = weight[irrep_idx[i]];
        if (wv != w0) bad = 1;
        ((float*)s_w)[i] = wv;
        ((float*)s_b)[i] = 0.f;
        if ((i & 3) == 0) s_gv[i >> 2] = g;
    }
    __syncthreads();
    for (int k = tid; k < nscalar; k += NT) {
        int idx = scalar_indices[k];
        float bv = bias[k];
        if (bv != 0.f) bad = 1;
        ((float*)s_b)[idx] = bv;
        atomicAdd(&s_scnt[group_idx[idx]], 1.f);
    }
    if (bad) atomicOr(&s_nonuni, 1);
    __syncthreads();
    if (tid < NG) {
        s_icnt[tid]  = 1.f / s_cnt[tid];
        s_iscnt[tid] = (s_scnt[tid] > 0.f) ? (1.f / s_scnt[tid]) : 0.f;
        s_scf[tid]   = s_scnt[tid];
    }
    if (tid == 0) {
        int m = 0;
        for (int g = 0; g < NG; g++) if (s_scnt[g] > 0.f) m |= (1 << g);
        s_umask = m;
    }
    __syncthreads();

    // ---------------- row-invariant per-lane state ------------------------------
    const int lane = tid & 31;
    const int wid  = tid >> 5;

    unsigned gp = 0;                 // packed group id per vector: 2 bits x VPT
    #pragma unroll
    for (int i = 0; i < VPT; i++) {
        int vi = lane + 32 * i;
        int g  = (vi < nvec) ? s_gv[vi] : 3;
        gp |= (unsigned)g << (2 * i);
    }
    const int  umask = s_umask;
    const bool uni   = (s_nonuni == 0);   // uniform weight & zero bias fast path
    const int  totw  = gridDim.x * WPB;

    // ---------------- warp-per-row main loop: NO barriers, row in registers -----
    for (int row = blockIdx.x * WPB + wid; row < np; row += totw) {
        const float4* xr = (const float4*)(x + (size_t)row * dim);

        float4 v[VPT];
        #pragma unroll
        for (int i = 0; i < VPT; i++) {
            int vi = lane + 32 * i;
            v[i] = (vi < nvec) ? xr[vi] : make_float4(0.f, 0.f, 0.f, 0.f);
        }

        // per-thread per-group partials: a = sum x^2; u = sum x (scalar groups)
        float a0 = 0.f, a1 = 0.f, a2 = 0.f, a3 = 0.f;
        float u0 = 0.f, u1 = 0.f, u2 = 0.f, u3 = 0.f;
        #pragma unroll
        for (int i = 0; i < VPT; i++) {
            float4 t = v[i];
            float s2 = t.x * t.x + t.y * t.y + t.z * t.z + t.w * t.w;
            float s1 = t.x + t.y + t.z + t.w;
            int g = (gp >> (2 * i)) & 3;
            if      (g == 0) { a0 += s2; if (umask & 1) u0 += s1; }
            else if (g == 1) { a1 += s2; if (umask & 2) u1 += s1; }
            else if (g == 2) { a2 += s2; if (umask & 4) u2 += s1; }
            else             { a3 += s2; if (umask & 8) u3 += s1; }
        }

        // butterflies: ssq always; scalar-sum chains only where a group has scalars
        BFLY(a0); BFLY(a1); BFLY(a2); BFLY(a3);
        if (umask & 1) { BFLY(u0); }
        if (umask & 2) { BFLY(u1); }
        if (umask & 4) { BFLY(u2); }
        if (umask & 8) { BFLY(u3); }

        // per-group stats: m_g = scalar mean (0 for non-scalar groups)
        // var_g = (ssq_g + m*(m*scnt_g - 2*ssum_g)) / cnt_g
        float m0 = u0 * s_iscnt[0], m1 = u1 * s_iscnt[1];
        float m2 = u2 * s_iscnt[2], m3 = u3 * s_iscnt[3];
        float r0 = rsqrtf(fmaf(m0, fmaf(m0, s_scf[0], -2.f * u0), a0) * s_icnt[0] + EPS_VAL);
        float r1 = rsqrtf(fmaf(m1, fmaf(m1, s_scf[1], -2.f * u1), a1) * s_icnt[1] + EPS_VAL);
        float r2 = rsqrtf(fmaf(m2, fmaf(m2, s_scf[2], -2.f * u2), a2) * s_icnt[2] + EPS_VAL);
        float r3 = rsqrtf(fmaf(m3, fmaf(m3, s_scf[3], -2.f * u3), a3) * s_icnt[3] + EPS_VAL);

        float4* orow = (float4*)(out + (size_t)row * dim);
        if (uni) {
            // fast path: uniform weight w0, zero bias -> no shared reads at all
            float rw0 = r0 * w0, rw1 = r1 * w0, rw2 = r2 * w0, rw3 = r3 * w0;
            #pragma unroll
            for (int i = 0; i < VPT; i++) {
                int vi = lane + 32 * i;
                if (vi < nvec) {
                    int g = (gp >> (2 * i)) & 3;
                    float mm = sel4(g, m0, m1, m2, m3);
                    float rw = sel4(g, rw0, rw1, rw2, rw3);
                    float4 t = v[i];
                    float4 o;
                    o.x = (t.x - mm) * rw;
                    o.y = (t.y - mm) * rw;
                    o.z = (t.z - mm) * rw;
                    o.w = (t.w - mm) * rw;
                    orow[vi] = o;
                }
            }
        } else {
            // general path: per-element weight/bias from shared memory
            #pragma unroll
            for (int i = 0; i < VPT; i++) {
                int vi = lane + 32 * i;
                if (vi < nvec) {
                    int g = (gp >> (2 * i)) & 3;
                    float mm = sel4(g, m0, m1, m2, m3);
                    float rr = sel4(g, r0, r1, r2, r3);
                    float4 t = v[i];
                    float4 w = s_w[vi];
                    float4 b = s_b[vi];
                    float4 o;
                    o.x = (t.x - mm) * rr * w.x + b.x;
                    o.y = (t.y - mm) * rr * w.y + b.y;
                    o.z = (t.z - mm) * rr * w.z + b.z;
                    o.w = (t.w - mm) * rr * w.w + b.w;
                    orow[vi] = o;
                }
            }
        }
    }
}

extern "C" void kernel_launch(void* const* d_in, const int* in_sizes, int n_in,
                              void* d_out, int out_size)
{
    const float* x              = (const float*)d_in[0];
    const float* weight         = (const float*)d_in[1];
    const float* bias           = (const float*)d_in[2];
    const int*   group_idx      = (const int*)  d_in[3];
    const int*   irrep_idx      = (const int*)  d_in[4];
    const int*   scalar_indices = (const int*)  d_in[5];
    // d_in[6] = scalar_group, unused (each scalar group coincides with one irrep group)

    const int dim     = in_sizes[3];            // len(group_idx) == feature dim
    const int np      = in_sizes[0] / dim;      // number of points
    const int nscalar = in_sizes[5];

    int grid = 152 * 3;                         // 3 resident blocks/SM, 1 wave
    int maxb = (np + WPB - 1) / WPB;
    if (grid > maxb) grid = maxb;

    eqln_kernel<<<grid, NT>>>(x, weight, bias,
                              group_idx, irrep_idx, scalar_indices,
                              (float*)d_out, np, dim, nscalar);
}

// round 16
// speedup vs baseline: 1.4124x; 1.0111x over previous
#include <cuda_runtime.h>

#define EPS_VAL 1e-5f
#define NT      256            // 8 warps/block
#define WPB     8
#define MAXVEC  320
#define NG      4
#define VPT     10             // max float4 vectors per lane (dim <= 1280)

#define BFLY(val)                                    \
    _Pragma("unroll")                                \
    for (int _o = 16; _o > 0; _o >>= 1)              \
        val += __shfl_xor_sync(0xffffffffu, val, _o);

__device__ __forceinline__ float sel4(int g, float a, float b, float c, float d) {
    float lo = (g == 0) ? a : b;
    float hi = (g == 2) ? c : d;
    return (g < 2) ? lo : hi;
}

__device__ __forceinline__ void pf_l2(const void* p) {
    asm volatile("prefetch.global.L2 [%0];" :: "l"(p));
}

__global__ void __launch_bounds__(NT, 3)       // 3 blocks = 24 warps/SM
eqln_kernel(const float* __restrict__ x,
            const float* __restrict__ weight,
            const float* __restrict__ bias,
            const int*   __restrict__ group_idx,
            const int*   __restrict__ irrep_idx,
            const int*   __restrict__ scalar_indices,
            float*       __restrict__ out,
            int np, int dim, int nscalar)
{
    __shared__ float4 s_w[MAXVEC];       // weight[irrep_idx[i]] per element
    __shared__ float4 s_b[MAXVEC];       // bias scattered to full dim (0 elsewhere)
    __shared__ int    s_gv[MAXVEC];      // group id per float4 (groups 16B-aligned)
    __shared__ float  s_cnt[NG], s_scnt[NG];
    __shared__ float  s_icnt[NG], s_iscnt[NG], s_scf[NG];
    __shared__ int    s_umask, s_nonuni;

    const int tid  = threadIdx.x;
    const int nvec = dim >> 2;

    // ---------------- per-block metadata setup (amortized over ~180 rows) -------
    if (tid < NG) { s_cnt[tid] = 0.f; s_scnt[tid] = 0.f; }
    if (tid == 0) s_nonuni = 0;
    __syncthreads();

    const float w0 = weight[0];
    int bad = 0;
    for (int i = tid; i < dim; i += NT) {
        int g = group_idx[i];
        atomicAdd(&s_cnt[g], 1.f);
        float wv = weight[irrep_idx[i]];
        if (wv != w0) bad = 1;
        ((float*)s_w)[i] = wv;
        ((float*)s_b)[i] = 0.f;
        if ((i & 3) == 0) s_gv[i >> 2] = g;
    }
    __syncthreads();
    for (int k = tid; k < nscalar; k += NT) {
        int idx = scalar_indices[k];
        float bv = bias[k];
        if (bv != 0.f) bad = 1;
        ((float*)s_b)[idx] = bv;
        atomicAdd(&s_scnt[group_idx[idx]], 1.f);
    }
    if (bad) atomicOr(&s_nonuni, 1);
    __syncthreads();
    if (tid < NG) {
        s_icnt[tid]  = 1.f / s_cnt[tid];
        s_iscnt[tid] = (s_scnt[tid] > 0.f) ? (1.f / s_scnt[tid]) : 0.f;
        s_scf[tid]   = s_scnt[tid];
    }
    if (tid == 0) {
        int m = 0;
        for (int g = 0; g < NG; g++) if (s_scnt[g] > 0.f) m |= (1 << g);
        s_umask = m;
    }
    __syncthreads();

    // ---------------- row-invariant per-lane state ------------------------------
    const int lane = tid & 31;
    const int wid  = tid >> 5;

    unsigned gp = 0;                 // packed group id per vector: 2 bits x VPT
    #pragma unroll
    for (int i = 0; i < VPT; i++) {
        int vi = lane + 32 * i;
        int g  = (vi < nvec) ? s_gv[vi] : 3;
        gp |= (unsigned)g << (2 * i);
    }
    const int  umask = s_umask;
    const bool uni   = (s_nonuni == 0);   // uniform weight & zero bias fast path
    const int  totw  = gridDim.x * WPB;

    const int rowbytes = dim * 4;    // bytes per row (multiple of 16)

    // ---------------- warp-per-row main loop: NO barriers, row in registers -----
    for (int row = blockIdx.x * WPB + wid; row < np; row += totw) {
        const float4* xr = (const float4*)(x + (size_t)row * dim);

        float4 v[VPT];
        #pragma unroll
        for (int i = 0; i < VPT; i++) {
            int vi = lane + 32 * i;
            v[i] = (vi < nvec) ? xr[vi] : make_float4(0.f, 0.f, 0.f, 0.f);
        }

        // ---- L2 prefetch of the NEXT row: keeps the DRAM pipe fed during the
        // compute/butterfly/store phase at zero register / zero L1-data cost.
        {
            int nrow = row + totw;
            if (nrow < np) {
                const char* nx = (const char*)(x + (size_t)nrow * dim);
                int off0 = lane * 128;
                if (off0 < rowbytes) pf_l2(nx + off0);           // lines 0..31
                int off1 = (lane + 32) * 128;
                if (off1 < rowbytes) pf_l2(nx + off1);           // lines 32..36
            }
        }

        // per-thread per-group partials: a = sum x^2; u = sum x (scalar groups)
        float a0 = 0.f, a1 = 0.f, a2 = 0.f, a3 = 0.f;
        float u0 = 0.f, u1 = 0.f, u2 = 0.f, u3 = 0.f;
        #pragma unroll
        for (int i = 0; i < VPT; i++) {
            float4 t = v[i];
            float s2 = t.x * t.x + t.y * t.y + t.z * t.z + t.w * t.w;
            float s1 = t.x + t.y + t.z + t.w;
            int g = (gp >> (2 * i)) & 3;
            if      (g == 0) { a0 += s2; if (umask & 1) u0 += s1; }
            else if (g == 1) { a1 += s2; if (umask & 2) u1 += s1; }
            else if (g == 2) { a2 += s2; if (umask & 4) u2 += s1; }
            else             { a3 += s2; if (umask & 8) u3 += s1; }
        }

        // butterflies: ssq always; scalar-sum chains only where a group has scalars
        BFLY(a0); BFLY(a1); BFLY(a2); BFLY(a3);
        if (umask & 1) { BFLY(u0); }
        if (umask & 2) { BFLY(u1); }
        if (umask & 4) { BFLY(u2); }
        if (umask & 8) { BFLY(u3); }

        // per-group stats: m_g = scalar mean (0 for non-scalar groups)
        // var_g = (ssq_g + m*(m*scnt_g - 2*ssum_g)) / cnt_g
        float m0 = u0 * s_iscnt[0], m1 = u1 * s_iscnt[1];
        float m2 = u2 * s_iscnt[2], m3 = u3 * s_iscnt[3];
        float r0 = rsqrtf(fmaf(m0, fmaf(m0, s_scf[0], -2.f * u0), a0) * s_icnt[0] + EPS_VAL);
        float r1 = rsqrtf(fmaf(m1, fmaf(m1, s_scf[1], -2.f * u1), a1) * s_icnt[1] + EPS_VAL);
        float r2 = rsqrtf(fmaf(m2, fmaf(m2, s_scf[2], -2.f * u2), a2) * s_icnt[2] + EPS_VAL);
        float r3 = rsqrtf(fmaf(m3, fmaf(m3, s_scf[3], -2.f * u3), a3) * s_icnt[3] + EPS_VAL);

        float4* orow = (float4*)(out + (size_t)row * dim);
        if (uni) {
            // fast path: uniform weight w0, zero bias -> no shared reads at all
            float rw0 = r0 * w0, rw1 = r1 * w0, rw2 = r2 * w0, rw3 = r3 * w0;
            #pragma unroll
            for (int i = 0; i < VPT; i++) {
                int vi = lane + 32 * i;
                if (vi < nvec) {
                    int g = (gp >> (2 * i)) & 3;
                    float mm = sel4(g, m0, m1, m2, m3);
                    float rw = sel4(g, rw0, rw1, rw2, rw3);
                    float4 t = v[i];
                    float4 o;
                    o.x = (t.x - mm) * rw;
                    o.y = (t.y - mm) * rw;
                    o.z = (t.z - mm) * rw;
                    o.w = (t.w - mm) * rw;
                    orow[vi] = o;
                }
            }
        } else {
            // general path: per-element weight/bias from shared memory
            #pragma unroll
            for (int i = 0; i < VPT; i++) {
                int vi = lane + 32 * i;
                if (vi < nvec) {
                    int g = (gp >> (2 * i)) & 3;
                    float mm = sel4(g, m0, m1, m2, m3);
                    float rr = sel4(g, r0, r1, r2, r3);
                    float4 t = v[i];
                    float4 w = s_w[vi];
                    float4 b = s_b[vi];
                    float4 o;
                    o.x = (t.x - mm) * rr * w.x + b.x;
                    o.y = (t.y - mm) * rr * w.y + b.y;
                    o.z = (t.z - mm) * rr * w.z + b.z;
                    o.w = (t.w - mm) * rr * w.w + b.w;
                    orow[vi] = o;
                }
            }
        }
    }
}

extern "C" void kernel_launch(void* const* d_in, const int* in_sizes, int n_in,
                              void* d_out, int out_size)
{
    const float* x              = (const float*)d_in[0];
    const float* weight         = (const float*)d_in[1];
    const float* bias           = (const float*)d_in[2];
    const int*   group_idx      = (const int*)  d_in[3];
    const int*   irrep_idx      = (const int*)  d_in[4];
    const int*   scalar_indices = (const int*)  d_in[5];
    // d_in[6] = scalar_group, unused (each scalar group coincides with one irrep group)

    const int dim     = in_sizes[3];            // len(group_idx) == feature dim
    const int np      = in_sizes[0] / dim;      // number of points
    const int nscalar = in_sizes[5];

    int grid = 152 * 3;                         // 3 resident blocks/SM, 1 wave
    int maxb = (np + WPB - 1) / WPB;
    if (grid > maxb) grid = maxb;

    eqln_kernel<<<grid, NT>>>(x, weight, bias,
                              group_idx, irrep_idx, scalar_indices,
                              (float*)d_out, np, dim, nscalar);
}